// round 3
// baseline (speedup 1.0000x reference)
#include <cuda_runtime.h>
#include <cstdint>
#include <cstdio>

#define B_   8
#define C_   768
#define L_   4096
#define NH_  12
#define D_   64
#define BH_  (B_*NH_)
#define PADD 68
#define SPAD 136

// ---------------- scratch (device globals: allocation-free rule) ----------------
__device__ float g_q[(size_t)B_ * C_ * L_];
__device__ float g_k[(size_t)B_ * C_ * L_];
__device__ float g_v[(size_t)B_ * C_ * L_];
__device__ float g_o[(size_t)B_ * C_ * L_];
__device__ float g_beta[(size_t)BH_ * L_];

__device__ __forceinline__ uint32_t f2tf(float f) {
    uint32_t r;
    asm("cvt.rna.tf32.f32 %0, %1;" : "=r"(r) : "f"(f));
    return r;
}

__device__ __forceinline__ void mma_tf32(float c[4], const uint32_t a[4], const uint32_t b[2]) {
    asm volatile(
        "mma.sync.aligned.m16n8k8.row.col.f32.tf32.tf32.f32 "
        "{%0,%1,%2,%3}, {%4,%5,%6,%7}, {%8,%9}, {%0,%1,%2,%3};"
        : "+f"(c[0]), "+f"(c[1]), "+f"(c[2]), "+f"(c[3])
        : "r"(a[0]), "r"(a[1]), "r"(a[2]), "r"(a[3]), "r"(b[0]), "r"(b[1]));
}

// ---------------- tf32 tensor-core GEMM ----------------
// Computes Out[(b*C+n)*L + l] = epi( sum_k A[(b*C+k)*L + l] * W[k*C + n] )
// A is [B][C][L] (l contiguous). CTA tile 128(l) x 128(n). 8 warps, warp tile 32x64.
// EPI=0: silu. EPI=1: add residual R, final output.
// NZ=3: blockIdx.z selects (W0->O0, W1->O1, W2->O2). NZ=1: W0->O0 only.
template<int EPI, int NZ>
__global__ __launch_bounds__(256) void gemm_tf32(
    const float* __restrict__ A,
    const float* __restrict__ W0, const float* __restrict__ W1, const float* __restrict__ W2,
    const float* __restrict__ R,
    float* __restrict__ O0, float* __restrict__ O1, float* __restrict__ O2)
{
    __shared__ uint32_t As[2][16][SPAD];
    __shared__ uint32_t Bs[2][16][SPAD];

    const int tid  = threadIdx.x;
    const int wid  = tid >> 5;
    const int lane = tid & 31;
    const int m0   = blockIdx.x * 128;
    const int b    = m0 >> 12;
    const int l0   = m0 & 4095;
    const int n0   = blockIdx.y * 128;

    const float* W;
    float* Out;
    if (NZ == 3) {
        const int z = blockIdx.z;
        W   = (z == 0) ? W0 : (z == 1) ? W1 : W2;
        Out = (z == 0) ? O0 : (z == 1) ? O1 : O2;
    } else {
        W = W0; Out = O0;
    }
    const float* Ab = A + (size_t)b * C_ * L_ + l0;

    // global loader indices: 16 rows x 128 cols, 2 float4 per thread
    const int lk = tid >> 5;               // 0..7 (+8 second pass)
    const int lc = (tid & 31) << 2;        // 0..124

    // warp tile
    const int wm = (wid & 3) * 32;
    const int wn = (wid >> 2) * 64;
    const int g  = lane >> 2;
    const int tg = lane & 3;

    float acc[2][8][4];
#pragma unroll
    for (int mf = 0; mf < 2; mf++)
#pragma unroll
        for (int j = 0; j < 8; j++)
#pragma unroll
            for (int r = 0; r < 4; r++) acc[mf][j][r] = 0.f;

    float4 pa0, pa1, pw0, pw1;
    pa0 = *(const float4*)(Ab + (size_t)lk * L_ + lc);
    pa1 = *(const float4*)(Ab + (size_t)(lk + 8) * L_ + lc);
    pw0 = *(const float4*)(W + (size_t)lk * C_ + n0 + lc);
    pw1 = *(const float4*)(W + (size_t)(lk + 8) * C_ + n0 + lc);
    {
        uint32_t* d0 = &As[0][lk][lc];
        uint32_t* d1 = &As[0][lk + 8][lc];
        d0[0] = f2tf(pa0.x); d0[1] = f2tf(pa0.y); d0[2] = f2tf(pa0.z); d0[3] = f2tf(pa0.w);
        d1[0] = f2tf(pa1.x); d1[1] = f2tf(pa1.y); d1[2] = f2tf(pa1.z); d1[3] = f2tf(pa1.w);
        uint32_t* e0 = &Bs[0][lk][lc];
        uint32_t* e1 = &Bs[0][lk + 8][lc];
        e0[0] = f2tf(pw0.x); e0[1] = f2tf(pw0.y); e0[2] = f2tf(pw0.z); e0[3] = f2tf(pw0.w);
        e1[0] = f2tf(pw1.x); e1[1] = f2tf(pw1.y); e1[2] = f2tf(pw1.z); e1[3] = f2tf(pw1.w);
    }
    __syncthreads();

    for (int k0 = 0; k0 < C_; k0 += 16) {
        const int  buf  = (k0 >> 4) & 1;
        const bool more = (k0 + 16) < C_;
        if (more) {
            pa0 = *(const float4*)(Ab + (size_t)(k0 + 16 + lk) * L_ + lc);
            pa1 = *(const float4*)(Ab + (size_t)(k0 + 24 + lk) * L_ + lc);
            pw0 = *(const float4*)(W + (size_t)(k0 + 16 + lk) * C_ + n0 + lc);
            pw1 = *(const float4*)(W + (size_t)(k0 + 24 + lk) * C_ + n0 + lc);
        }
#pragma unroll
        for (int ks = 0; ks < 16; ks += 8) {
            uint32_t af[2][4], bf[8][2];
#pragma unroll
            for (int mf = 0; mf < 2; mf++) {
                const int mr = wm + mf * 16 + g;
                af[mf][0] = As[buf][ks + tg][mr];
                af[mf][1] = As[buf][ks + tg][mr + 8];
                af[mf][2] = As[buf][ks + 4 + tg][mr];
                af[mf][3] = As[buf][ks + 4 + tg][mr + 8];
            }
#pragma unroll
            for (int j = 0; j < 8; j++) {
                const int nc = wn + j * 8 + g;
                bf[j][0] = Bs[buf][ks + tg][nc];
                bf[j][1] = Bs[buf][ks + 4 + tg][nc];
            }
#pragma unroll
            for (int mf = 0; mf < 2; mf++)
#pragma unroll
                for (int j = 0; j < 8; j++)
                    mma_tf32(acc[mf][j], af[mf], bf[j]);
        }
        if (more) {
            uint32_t* d0 = &As[buf ^ 1][lk][lc];
            uint32_t* d1 = &As[buf ^ 1][lk + 8][lc];
            d0[0] = f2tf(pa0.x); d0[1] = f2tf(pa0.y); d0[2] = f2tf(pa0.z); d0[3] = f2tf(pa0.w);
            d1[0] = f2tf(pa1.x); d1[1] = f2tf(pa1.y); d1[2] = f2tf(pa1.z); d1[3] = f2tf(pa1.w);
            uint32_t* e0 = &Bs[buf ^ 1][lk][lc];
            uint32_t* e1 = &Bs[buf ^ 1][lk + 8][lc];
            e0[0] = f2tf(pw0.x); e0[1] = f2tf(pw0.y); e0[2] = f2tf(pw0.z); e0[3] = f2tf(pw0.w);
            e1[0] = f2tf(pw1.x); e1[1] = f2tf(pw1.y); e1[2] = f2tf(pw1.z); e1[3] = f2tf(pw1.w);
        }
        __syncthreads();
    }

    // ---- epilogue: stage 32-n slices through smem, coalesced channel-major stores ----
    float* stage = (float*)&As[0][0][0];   // 32 x 132 floats, fits in As/Bs union
#pragma unroll 1
    for (int s = 0; s < 4; s++) {
#pragma unroll
        for (int mf = 0; mf < 2; mf++)
#pragma unroll
            for (int j = 0; j < 8; j++) {
                if (((wn + j * 8) >> 5) != s) continue;
                const int n = (wn + j * 8 + tg * 2) & 31;
                const int m = wm + mf * 16 + g;
                float v0 = acc[mf][j][0], v1 = acc[mf][j][1];
                float v2 = acc[mf][j][2], v3 = acc[mf][j][3];
                if (EPI == 0) {
                    v0 = v0 / (1.f + __expf(-v0));
                    v1 = v1 / (1.f + __expf(-v1));
                    v2 = v2 / (1.f + __expf(-v2));
                    v3 = v3 / (1.f + __expf(-v3));
                }
                stage[n * 132 + m]           = v0;
                stage[(n + 1) * 132 + m]     = v1;
                stage[n * 132 + m + 8]       = v2;
                stage[(n + 1) * 132 + m + 8] = v3;
            }
        __syncthreads();
        {
            const int nr   = tid >> 3;            // 0..31
            const int lcol = (tid & 7) << 4;      // 0..112
            const size_t gb = ((size_t)(b * C_ + n0 + s * 32 + nr)) * L_ + l0 + lcol;
            float v[16];
#pragma unroll
            for (int t = 0; t < 16; t++) v[t] = stage[nr * 132 + lcol + t];
            if (EPI == 1) {
                const float* r = R + gb;
#pragma unroll
                for (int t = 0; t < 16; t++) v[t] += r[t];
            }
            float* dst = Out + gb;
            *(float4*)(dst)      = *(float4*)(v);
            *(float4*)(dst + 4)  = *(float4*)(v + 4);
            *(float4*)(dst + 8)  = *(float4*)(v + 8);
            *(float4*)(dst + 12) = *(float4*)(v + 12);
        }
        __syncthreads();
    }
}

// ---------------- beta = sigmoid(t @ Wb), written [B][H][L] ----------------
__global__ __launch_bounds__(256) void beta_kernel(
    const float* __restrict__ X, const float* __restrict__ Wb,
    float* __restrict__ Beta)
{
    __shared__ float As[16][256];
    __shared__ float Ws[16][12];
    const int tid = threadIdx.x;
    const int m0  = blockIdx.x * 256;
    const int b   = m0 >> 12;
    const int l0  = m0 & 4095;
    const float* Ab = X + (size_t)b * C_ * L_ + l0;

    float acc[12];
#pragma unroll
    for (int h = 0; h < 12; h++) acc[h] = 0.f;

    for (int k0 = 0; k0 < C_; k0 += 16) {
#pragma unroll
        for (int kk = 0; kk < 16; kk++) As[kk][tid] = Ab[(size_t)(k0 + kk) * L_ + tid];
        if (tid < 192) Ws[tid / 12][tid % 12] = Wb[(size_t)(k0 + tid / 12) * 12 + (tid % 12)];
        __syncthreads();
#pragma unroll
        for (int kk = 0; kk < 16; kk++) {
            float a = As[kk][tid];
#pragma unroll
            for (int h = 0; h < 12; h++) acc[h] += a * Ws[kk][h];
        }
        __syncthreads();
    }
#pragma unroll
    for (int h = 0; h < 12; h++) {
        Beta[((size_t)(b * NH_ + h)) * L_ + l0 + tid] = 1.f / (1.f + __expf(-acc[h]));
    }
}

// ---------------- delta rule: 1 CTA per (b,h), 64 sequential chunks ----------------
__global__ __launch_bounds__(256) void delta_kernel(
    const float* __restrict__ gq, const float* __restrict__ gk,
    const float* __restrict__ gv, const float* __restrict__ gb,
    float* __restrict__ go)
{
    extern __shared__ float sm[];
    float* S   = sm;                 // [d][e]   state
    float* qst = S   + 64 * PADD;    // [d][i]   q transposed (contract-major)
    float* kst = qst + 64 * PADD;    // [d][i]
    float* ks  = kst + 64 * PADD;    // [i][d]   k row-form (for S update)
    float* U   = ks  + 64 * PADD;    // [i][e]   rhs -> solved U
    float* T   = U   + 64 * PADD;    // [i][j]   tri matrix; reused as O staging [e][i]
    float* QKt = T   + 64 * PADD;    // [j][i]   masked q.k (transposed)
    float* bvec = QKt + 64 * PADD;   // [64]

    const int tid = threadIdx.x;
    const int bh  = blockIdx.x;
    const int b   = bh / NH_, h = bh % NH_;
    const size_t base = ((size_t)(b * C_ + h * D_)) * L_;
    const float* qgp = gq + base;
    const float* kgp = gk + base;
    const float* vgp = gv + base;
    const float* bgp = gb + (size_t)bh * L_;
    float* ogp = go + base;

    for (int i = tid; i < 64 * PADD; i += 256) S[i] = 0.f;
    __syncthreads();

    const int ri  = (tid >> 4) << 2;
    const int rj  = (tid & 15) << 2;
    const int ld  = tid >> 2;
    const int li0 = (tid & 3) << 4;

    for (int c = 0; c < 64; c++) {
        const int off = c * 64;
        {
            const float* qrow = qgp + (size_t)ld * L_ + off + li0;
            const float* krow = kgp + (size_t)ld * L_ + off + li0;
            const float* vrow = vgp + (size_t)ld * L_ + off + li0;
#pragma unroll
            for (int u = 0; u < 16; u += 4) {
                float4 qv = *(const float4*)(qrow + u);
                float4 kv = *(const float4*)(krow + u);
                float4 vv = *(const float4*)(vrow + u);
                *(float4*)&qst[ld * PADD + li0 + u] = qv;
                *(float4*)&kst[ld * PADD + li0 + u] = kv;
                ks[(li0 + u + 0) * PADD + ld] = kv.x;
                ks[(li0 + u + 1) * PADD + ld] = kv.y;
                ks[(li0 + u + 2) * PADD + ld] = kv.z;
                ks[(li0 + u + 3) * PADD + ld] = kv.w;
                U[(li0 + u + 0) * PADD + ld] = vv.x;
                U[(li0 + u + 1) * PADD + ld] = vv.y;
                U[(li0 + u + 2) * PADD + ld] = vv.z;
                U[(li0 + u + 3) * PADD + ld] = vv.w;
            }
            if (tid < 64) bvec[tid] = bgp[off + tid];
        }
        __syncthreads();
        {
            const int tok = tid >> 2;
            const int d0  = (tid & 3) << 4;
            float sq = 0.f, sk = 0.f;
#pragma unroll
            for (int d = d0; d < d0 + 16; d++) {
                float qv = qst[d * PADD + tok]; sq += qv * qv;
                float kv = kst[d * PADD + tok]; sk += kv * kv;
            }
            sq += __shfl_xor_sync(0xFFFFFFFFu, sq, 1);
            sq += __shfl_xor_sync(0xFFFFFFFFu, sq, 2);
            sk += __shfl_xor_sync(0xFFFFFFFFu, sk, 1);
            sk += __shfl_xor_sync(0xFFFFFFFFu, sk, 2);
            const float rq = rsqrtf(sq + 1e-6f);
            const float rk = rsqrtf(sk + 1e-6f);
#pragma unroll
            for (int d = d0; d < d0 + 16; d++) {
                qst[d * PADD + tok] *= rq;
                kst[d * PADD + tok] *= rk;
                ks[tok * PADD + d]  *= rk;
            }
        }
        __syncthreads();
        {
            float aT[4][4], aQ[4][4], aU[4][4];
#pragma unroll
            for (int u = 0; u < 4; u++)
#pragma unroll
                for (int w = 0; w < 4; w++) { aT[u][w] = 0.f; aQ[u][w] = 0.f; aU[u][w] = 0.f; }
            for (int d = 0; d < 64; d++) {
                float4 a4 = *(float4*)&kst[d * PADD + ri];
                float4 b1 = *(float4*)&kst[d * PADD + rj];
                float4 b2 = *(float4*)&qst[d * PADD + rj];
                float4 b3 = *(float4*)&S[d * PADD + rj];
                float av[4]  = {a4.x, a4.y, a4.z, a4.w};
                float b1v[4] = {b1.x, b1.y, b1.z, b1.w};
                float b2v[4] = {b2.x, b2.y, b2.z, b2.w};
                float b3v[4] = {b3.x, b3.y, b3.z, b3.w};
#pragma unroll
                for (int u = 0; u < 4; u++)
#pragma unroll
                    for (int w = 0; w < 4; w++) {
                        aT[u][w] += av[u] * b1v[w];
                        aQ[u][w] += av[u] * b2v[w];
                        aU[u][w] += av[u] * b3v[w];
                    }
            }
#pragma unroll
            for (int u = 0; u < 4; u++) {
                const int gi = ri + u;
#pragma unroll
                for (int w = 0; w < 4; w++) {
                    const int gj = rj + w;
                    T[gi * PADD + gj]   = (gj < gi) ? bvec[gi] * aT[u][w] : (gi == gj ? 1.f : 0.f);
                    QKt[gi * PADD + gj] = (gi <= gj) ? aQ[u][w] : 0.f;
                    const int idx = gi * PADD + gj;
                    U[idx] = bvec[gi] * (U[idx] - aU[u][w]);
                }
            }
        }
        __syncthreads();
        if (tid < 64) {
            const int e = tid;
            for (int i = 1; i < 64; i++) {
                const float* Trow = &T[i * PADD];
                float s0 = 0.f, s1 = 0.f, s2 = 0.f, s3 = 0.f;
                int j = 0;
                for (; j + 4 <= i; j += 4) {
                    s0 += Trow[j]     * U[(j)     * PADD + e];
                    s1 += Trow[j + 1] * U[(j + 1) * PADD + e];
                    s2 += Trow[j + 2] * U[(j + 2) * PADD + e];
                    s3 += Trow[j + 3] * U[(j + 3) * PADD + e];
                }
                for (; j < i; j++) s0 += Trow[j] * U[j * PADD + e];
                U[i * PADD + e] -= (s0 + s1) + (s2 + s3);
            }
        }
        __syncthreads();
        {
            float aO[4][4];
#pragma unroll
            for (int u = 0; u < 4; u++)
#pragma unroll
                for (int w = 0; w < 4; w++) aO[u][w] = 0.f;
            for (int d = 0; d < 64; d++) {
                float4 a4 = *(float4*)&qst[d * PADD + ri];
                float4 b4 = *(float4*)&S[d * PADD + rj];
                float av[4] = {a4.x, a4.y, a4.z, a4.w};
                float bv[4] = {b4.x, b4.y, b4.z, b4.w};
#pragma unroll
                for (int u = 0; u < 4; u++)
#pragma unroll
                    for (int w = 0; w < 4; w++) aO[u][w] += av[u] * bv[w];
            }
            for (int j2 = 0; j2 < 64; j2++) {
                float4 a4 = *(float4*)&QKt[j2 * PADD + ri];
                float4 b4 = *(float4*)&U[j2 * PADD + rj];
                float av[4] = {a4.x, a4.y, a4.z, a4.w};
                float bv[4] = {b4.x, b4.y, b4.z, b4.w};
#pragma unroll
                for (int u = 0; u < 4; u++)
#pragma unroll
                    for (int w = 0; w < 4; w++) aO[u][w] += av[u] * bv[w];
            }
#pragma unroll
            for (int u = 0; u < 4; u++)
#pragma unroll
                for (int w = 0; w < 4; w++)
                    T[(rj + w) * PADD + (ri + u)] = aO[u][w];
        }
        __syncthreads();
        {
            float aS[4][4];
#pragma unroll
            for (int u = 0; u < 4; u++)
#pragma unroll
                for (int w = 0; w < 4; w++) aS[u][w] = 0.f;
            for (int i2 = 0; i2 < 64; i2++) {
                float4 a4 = *(float4*)&ks[i2 * PADD + ri];
                float4 b4 = *(float4*)&U[i2 * PADD + rj];
                float av[4] = {a4.x, a4.y, a4.z, a4.w};
                float bv[4] = {b4.x, b4.y, b4.z, b4.w};
#pragma unroll
                for (int u = 0; u < 4; u++)
#pragma unroll
                    for (int w = 0; w < 4; w++) aS[u][w] += av[u] * bv[w];
            }
#pragma unroll
            for (int u = 0; u < 4; u++)
#pragma unroll
                for (int w = 0; w < 4; w++)
                    S[(ri + u) * PADD + rj + w] += aS[u][w];

            float* dst = ogp + (size_t)ld * L_ + off + li0;
#pragma unroll
            for (int u = 0; u < 16; u += 4)
                *(float4*)(dst + u) = *(float4*)&T[ld * PADD + li0 + u];
        }
        __syncthreads();
    }
}

// ---------------- launch ----------------
extern "C" void kernel_launch(void* const* d_in, const int* in_sizes, int n_in,
                              void* d_out, int out_size)
{
    const float* x  = (const float*)d_in[0];
    const float* Wq = (const float*)d_in[1];
    const float* Wk = (const float*)d_in[2];
    const float* Wv = (const float*)d_in[3];
    const float* Wb = (const float*)d_in[4];
    const float* Wo = (const float*)d_in[5];
    float* out = (float*)d_out;

    float *qp, *kp, *vp, *op, *bp;
    cudaGetSymbolAddress((void**)&qp, g_q);
    cudaGetSymbolAddress((void**)&kp, g_k);
    cudaGetSymbolAddress((void**)&vp, g_v);
    cudaGetSymbolAddress((void**)&op, g_o);
    cudaGetSymbolAddress((void**)&bp, g_beta);

    const int smemDelta = (7 * 64 * PADD + 64) * (int)sizeof(float);
    cudaFuncSetAttribute(delta_kernel, cudaFuncAttributeMaxDynamicSharedMemorySize, smemDelta);

    dim3 blk(256);
    // beta first so the fixed ncu capture (-s 5) lands on the qkv tf32 GEMM
    beta_kernel<<<128, blk>>>(x, Wb, bp);
    gemm_tf32<0, 3><<<dim3(256, 6, 3), blk>>>(x, Wq, Wk, Wv, nullptr, qp, kp, vp);
    delta_kernel<<<96, blk, smemDelta>>>(qp, kp, vp, bp, op);
    gemm_tf32<1, 1><<<dim3(256, 6, 1), blk>>>(op, Wo, nullptr, nullptr, x, out, nullptr, nullptr);
}

// round 4
// speedup vs baseline: 1.2497x; 1.2497x over previous
#include <cuda_runtime.h>
#include <cstdint>
#include <cstdio>

#define B_   8
#define C_   768
#define L_   4096
#define NH_  12
#define D_   64
#define BH_  (B_*NH_)
#define SPAD 136
#define DP   72   // delta smem row pad (floats): conflict-free mma frag loads

// ---------------- scratch ----------------
__device__ float g_q[(size_t)B_ * C_ * L_];
__device__ float g_k[(size_t)B_ * C_ * L_];
__device__ float g_v[(size_t)B_ * C_ * L_];
__device__ float g_o[(size_t)B_ * C_ * L_];
__device__ float g_beta[(size_t)BH_ * L_];

__device__ __forceinline__ uint32_t f2tf(float f) {
    uint32_t r;
    asm("cvt.rna.tf32.f32 %0, %1;" : "=r"(r) : "f"(f));
    return r;
}
__device__ __forceinline__ float tfbits(float f) {   // store tf32 bit pattern as float
    return __uint_as_float(f2tf(f));
}

__device__ __forceinline__ void mma_tf32(float c[4], const uint32_t a[4], const uint32_t b[2]) {
    asm volatile(
        "mma.sync.aligned.m16n8k8.row.col.f32.tf32.tf32.f32 "
        "{%0,%1,%2,%3}, {%4,%5,%6,%7}, {%8,%9}, {%0,%1,%2,%3};"
        : "+f"(c[0]), "+f"(c[1]), "+f"(c[2]), "+f"(c[3])
        : "r"(a[0]), "r"(a[1]), "r"(a[2]), "r"(a[3]), "r"(b[0]), "r"(b[1]));
}

// ---------------- tf32 tensor-core GEMM (unchanged from R3) ----------------
template<int EPI, int NZ>
__global__ __launch_bounds__(256) void gemm_tf32(
    const float* __restrict__ A,
    const float* __restrict__ W0, const float* __restrict__ W1, const float* __restrict__ W2,
    const float* __restrict__ R,
    float* __restrict__ O0, float* __restrict__ O1, float* __restrict__ O2)
{
    __shared__ uint32_t As[2][16][SPAD];
    __shared__ uint32_t Bs[2][16][SPAD];

    const int tid  = threadIdx.x;
    const int wid  = tid >> 5;
    const int lane = tid & 31;
    const int m0   = blockIdx.x * 128;
    const int b    = m0 >> 12;
    const int l0   = m0 & 4095;
    const int n0   = blockIdx.y * 128;

    const float* W;
    float* Out;
    if (NZ == 3) {
        const int z = blockIdx.z;
        W   = (z == 0) ? W0 : (z == 1) ? W1 : W2;
        Out = (z == 0) ? O0 : (z == 1) ? O1 : O2;
    } else {
        W = W0; Out = O0;
    }
    const float* Ab = A + (size_t)b * C_ * L_ + l0;

    const int lk = tid >> 5;
    const int lc = (tid & 31) << 2;

    const int wm = (wid & 3) * 32;
    const int wn = (wid >> 2) * 64;
    const int g  = lane >> 2;
    const int tg = lane & 3;

    float acc[2][8][4];
#pragma unroll
    for (int mf = 0; mf < 2; mf++)
#pragma unroll
        for (int j = 0; j < 8; j++)
#pragma unroll
            for (int r = 0; r < 4; r++) acc[mf][j][r] = 0.f;

    float4 pa0, pa1, pw0, pw1;
    pa0 = *(const float4*)(Ab + (size_t)lk * L_ + lc);
    pa1 = *(const float4*)(Ab + (size_t)(lk + 8) * L_ + lc);
    pw0 = *(const float4*)(W + (size_t)lk * C_ + n0 + lc);
    pw1 = *(const float4*)(W + (size_t)(lk + 8) * C_ + n0 + lc);
    {
        uint32_t* d0 = &As[0][lk][lc];
        uint32_t* d1 = &As[0][lk + 8][lc];
        d0[0] = f2tf(pa0.x); d0[1] = f2tf(pa0.y); d0[2] = f2tf(pa0.z); d0[3] = f2tf(pa0.w);
        d1[0] = f2tf(pa1.x); d1[1] = f2tf(pa1.y); d1[2] = f2tf(pa1.z); d1[3] = f2tf(pa1.w);
        uint32_t* e0 = &Bs[0][lk][lc];
        uint32_t* e1 = &Bs[0][lk + 8][lc];
        e0[0] = f2tf(pw0.x); e0[1] = f2tf(pw0.y); e0[2] = f2tf(pw0.z); e0[3] = f2tf(pw0.w);
        e1[0] = f2tf(pw1.x); e1[1] = f2tf(pw1.y); e1[2] = f2tf(pw1.z); e1[3] = f2tf(pw1.w);
    }
    __syncthreads();

    for (int k0 = 0; k0 < C_; k0 += 16) {
        const int  buf  = (k0 >> 4) & 1;
        const bool more = (k0 + 16) < C_;
        if (more) {
            pa0 = *(const float4*)(Ab + (size_t)(k0 + 16 + lk) * L_ + lc);
            pa1 = *(const float4*)(Ab + (size_t)(k0 + 24 + lk) * L_ + lc);
            pw0 = *(const float4*)(W + (size_t)(k0 + 16 + lk) * C_ + n0 + lc);
            pw1 = *(const float4*)(W + (size_t)(k0 + 24 + lk) * C_ + n0 + lc);
        }
#pragma unroll
        for (int ks = 0; ks < 16; ks += 8) {
            uint32_t af[2][4], bf[8][2];
#pragma unroll
            for (int mf = 0; mf < 2; mf++) {
                const int mr = wm + mf * 16 + g;
                af[mf][0] = As[buf][ks + tg][mr];
                af[mf][1] = As[buf][ks + tg][mr + 8];
                af[mf][2] = As[buf][ks + 4 + tg][mr];
                af[mf][3] = As[buf][ks + 4 + tg][mr + 8];
            }
#pragma unroll
            for (int j = 0; j < 8; j++) {
                const int nc = wn + j * 8 + g;
                bf[j][0] = Bs[buf][ks + tg][nc];
                bf[j][1] = Bs[buf][ks + 4 + tg][nc];
            }
#pragma unroll
            for (int mf = 0; mf < 2; mf++)
#pragma unroll
                for (int j = 0; j < 8; j++)
                    mma_tf32(acc[mf][j], af[mf], bf[j]);
        }
        if (more) {
            uint32_t* d0 = &As[buf ^ 1][lk][lc];
            uint32_t* d1 = &As[buf ^ 1][lk + 8][lc];
            d0[0] = f2tf(pa0.x); d0[1] = f2tf(pa0.y); d0[2] = f2tf(pa0.z); d0[3] = f2tf(pa0.w);
            d1[0] = f2tf(pa1.x); d1[1] = f2tf(pa1.y); d1[2] = f2tf(pa1.z); d1[3] = f2tf(pa1.w);
            uint32_t* e0 = &Bs[buf ^ 1][lk][lc];
            uint32_t* e1 = &Bs[buf ^ 1][lk + 8][lc];
            e0[0] = f2tf(pw0.x); e0[1] = f2tf(pw0.y); e0[2] = f2tf(pw0.z); e0[3] = f2tf(pw0.w);
            e1[0] = f2tf(pw1.x); e1[1] = f2tf(pw1.y); e1[2] = f2tf(pw1.z); e1[3] = f2tf(pw1.w);
        }
        __syncthreads();
    }

    float* stage = (float*)&As[0][0][0];
#pragma unroll 1
    for (int s = 0; s < 4; s++) {
#pragma unroll
        for (int mf = 0; mf < 2; mf++)
#pragma unroll
            for (int j = 0; j < 8; j++) {
                if (((wn + j * 8) >> 5) != s) continue;
                const int n = (wn + j * 8 + tg * 2) & 31;
                const int m = wm + mf * 16 + g;
                float v0 = acc[mf][j][0], v1 = acc[mf][j][1];
                float v2 = acc[mf][j][2], v3 = acc[mf][j][3];
                if (EPI == 0) {
                    v0 = v0 / (1.f + __expf(-v0));
                    v1 = v1 / (1.f + __expf(-v1));
                    v2 = v2 / (1.f + __expf(-v2));
                    v3 = v3 / (1.f + __expf(-v3));
                }
                stage[n * 132 + m]           = v0;
                stage[(n + 1) * 132 + m]     = v1;
                stage[n * 132 + m + 8]       = v2;
                stage[(n + 1) * 132 + m + 8] = v3;
            }
        __syncthreads();
        {
            const int nr   = tid >> 3;
            const int lcol = (tid & 7) << 4;
            const size_t gb = ((size_t)(b * C_ + n0 + s * 32 + nr)) * L_ + l0 + lcol;
            float v[16];
#pragma unroll
            for (int t = 0; t < 16; t++) v[t] = stage[nr * 132 + lcol + t];
            if (EPI == 1) {
                const float* r = R + gb;
#pragma unroll
                for (int t = 0; t < 16; t++) v[t] += r[t];
            }
            float* dst = Out + gb;
            *(float4*)(dst)      = *(float4*)(v);
            *(float4*)(dst + 4)  = *(float4*)(v + 4);
            *(float4*)(dst + 8)  = *(float4*)(v + 8);
            *(float4*)(dst + 12) = *(float4*)(v + 12);
        }
        __syncthreads();
    }
}

// ---------------- beta = sigmoid(t @ Wb) ----------------
__global__ __launch_bounds__(256) void beta_kernel(
    const float* __restrict__ X, const float* __restrict__ Wb,
    float* __restrict__ Beta)
{
    __shared__ float As[16][256];
    __shared__ float Ws[16][12];
    const int tid = threadIdx.x;
    const int m0  = blockIdx.x * 256;
    const int b   = m0 >> 12;
    const int l0  = m0 & 4095;
    const float* Ab = X + (size_t)b * C_ * L_ + l0;

    float acc[12];
#pragma unroll
    for (int h = 0; h < 12; h++) acc[h] = 0.f;

    for (int k0 = 0; k0 < C_; k0 += 16) {
#pragma unroll
        for (int kk = 0; kk < 16; kk++) As[kk][tid] = Ab[(size_t)(k0 + kk) * L_ + tid];
        if (tid < 192) Ws[tid / 12][tid % 12] = Wb[(size_t)(k0 + tid / 12) * 12 + (tid % 12)];
        __syncthreads();
#pragma unroll
        for (int kk = 0; kk < 16; kk++) {
            float a = As[kk][tid];
#pragma unroll
            for (int h = 0; h < 12; h++) acc[h] += a * Ws[kk][h];
        }
        __syncthreads();
    }
#pragma unroll
    for (int h = 0; h < 12; h++) {
        Beta[((size_t)(b * NH_ + h)) * L_ + l0 + tid] = 1.f / (1.f + __expf(-acc[h]));
    }
}

// ---------------- delta rule, tensor-core version ----------------
// 1 CTA per (b,h). 64 sequential chunks of 64 tokens. All 64x64x64 matmuls via
// tf32 mma m16n8k8 (8 warps, warp tile 16x32). State S kept fp32; tf32 shadow
// regenerated after each update. Triangular solve: blocked-16 forward subst.
__global__ __launch_bounds__(256) void delta_mma(
    const float* __restrict__ gq, const float* __restrict__ gk,
    const float* __restrict__ gv, const float* __restrict__ gb,
    float* __restrict__ go)
{
    extern __shared__ float sm[];
    float* S_f  = sm;               // [d][e] fp32 state
    float* S_t  = S_f  + 64 * DP;   // [d][e] tf32
    float* q_t  = S_t  + 64 * DP;   // [d][i] tf32 (reused as O stage [e][i] fp32)
    float* k_t  = q_t  + 64 * DP;   // [d][i] tf32
    float* kr_t = k_t  + 64 * DP;   // [i][d] tf32
    float* U_f  = kr_t + 64 * DP;   // [i][e] fp32 rhs -> U
    float* U_t  = U_f  + 64 * DP;   // [i][e] tf32
    float* W_f  = U_t  + 64 * DP;   // [i][j] fp32 unit-lower T
    float* QK_t = W_f  + 64 * DP;   // [j][i] tf32 masked QK (transposed)
    float* bv   = QK_t + 64 * DP;   // [64]

    const int tid  = threadIdx.x;
    const int wid  = tid >> 5;
    const int lane = tid & 31;
    const int wm   = (wid & 3) * 16;   // warp m block (i or d rows)
    const int wn   = (wid >> 2) * 32;  // warp n block
    const int g    = lane >> 2;
    const int tg   = lane & 3;
    const int i0   = wm + g;
    const int i1   = wm + g + 8;

    const int bh = blockIdx.x;
    const int b  = bh / NH_, h = bh % NH_;
    const size_t base = ((size_t)(b * C_ + h * D_)) * L_;
    const float* qgp = gq + base;
    const float* kgp = gk + base;
    const float* vgp = gv + base;
    const float* bgp = gb + (size_t)bh * L_;
    float* ogp = go + base;

    for (int i = tid; i < 2 * 64 * DP; i += 256) S_f[i] = 0.f;   // S_f and S_t
    __syncthreads();

    const int ld  = tid >> 2;          // 0..63 row for load/store
    const int li0 = (tid & 3) << 4;    // 0,16,32,48

    for (int c = 0; c < 64; c++) {
        const int off = c * 64;

        // ---- A: load q,k (raw fp32 into q_t/k_t), v (transposed into U_f), beta ----
        {
            const float* qrow = qgp + (size_t)ld * L_ + off + li0;
            const float* krow = kgp + (size_t)ld * L_ + off + li0;
            const float* vrow = vgp + (size_t)ld * L_ + off + li0;
#pragma unroll
            for (int u = 0; u < 16; u += 4) {
                float4 qv = *(const float4*)(qrow + u);
                float4 kv = *(const float4*)(krow + u);
                float4 vv = *(const float4*)(vrow + u);
                *(float4*)&q_t[ld * DP + li0 + u] = qv;
                *(float4*)&k_t[ld * DP + li0 + u] = kv;
                U_f[(li0 + u + 0) * DP + ld] = vv.x;
                U_f[(li0 + u + 1) * DP + ld] = vv.y;
                U_f[(li0 + u + 2) * DP + ld] = vv.z;
                U_f[(li0 + u + 3) * DP + ld] = vv.w;
            }
            if (tid < 64) bv[tid] = bgp[off + tid];
        }
        __syncthreads();

        // ---- B: l2norm q,k per token; convert to tf32; build kr_t ----
        {
            const int tok = tid >> 2;
            const int d0  = (tid & 3) << 4;
            float sq = 0.f, sk = 0.f;
#pragma unroll
            for (int d = d0; d < d0 + 16; d++) {
                float qv = q_t[d * DP + tok]; sq += qv * qv;
                float kv = k_t[d * DP + tok]; sk += kv * kv;
            }
            sq += __shfl_xor_sync(0xFFFFFFFFu, sq, 1);
            sq += __shfl_xor_sync(0xFFFFFFFFu, sq, 2);
            sk += __shfl_xor_sync(0xFFFFFFFFu, sk, 1);
            sk += __shfl_xor_sync(0xFFFFFFFFu, sk, 2);
            const float rq = rsqrtf(sq + 1e-6f);
            const float rk = rsqrtf(sk + 1e-6f);
#pragma unroll
            for (int d = d0; d < d0 + 16; d++) {
                q_t[d * DP + tok] = tfbits(q_t[d * DP + tok] * rq);
                float kv = k_t[d * DP + tok] * rk;
                float kb = tfbits(kv);
                k_t[d * DP + tok] = kb;
                kr_t[tok * DP + d] = kb;
            }
        }
        __syncthreads();

        // ---- C: mma set 1: T_raw = K K^T, QK = Q K^T, KS = K S  (contract d) ----
        {
            float aT[4][4], aQ[4][4], aS[4][4];
#pragma unroll
            for (int jt = 0; jt < 4; jt++)
#pragma unroll
                for (int r = 0; r < 4; r++) { aT[jt][r] = 0.f; aQ[jt][r] = 0.f; aS[jt][r] = 0.f; }

#pragma unroll
            for (int ks = 0; ks < 64; ks += 8) {
                uint32_t ak[4], aq[4];
                ak[0] = __float_as_uint(k_t[(ks + tg) * DP + i0]);
                ak[1] = __float_as_uint(k_t[(ks + tg) * DP + i1]);
                ak[2] = __float_as_uint(k_t[(ks + 4 + tg) * DP + i0]);
                ak[3] = __float_as_uint(k_t[(ks + 4 + tg) * DP + i1]);
                aq[0] = __float_as_uint(q_t[(ks + tg) * DP + i0]);
                aq[1] = __float_as_uint(q_t[(ks + tg) * DP + i1]);
                aq[2] = __float_as_uint(q_t[(ks + 4 + tg) * DP + i0]);
                aq[3] = __float_as_uint(q_t[(ks + 4 + tg) * DP + i1]);
#pragma unroll
                for (int jt = 0; jt < 4; jt++) {
                    const int nc = wn + jt * 8 + g;
                    uint32_t bk[2], bS[2];
                    bk[0] = __float_as_uint(k_t[(ks + tg) * DP + nc]);
                    bk[1] = __float_as_uint(k_t[(ks + 4 + tg) * DP + nc]);
                    bS[0] = __float_as_uint(S_t[(ks + tg) * DP + nc]);
                    bS[1] = __float_as_uint(S_t[(ks + 4 + tg) * DP + nc]);
                    mma_tf32(aT[jt], ak, bk);
                    mma_tf32(aQ[jt], aq, bk);
                    mma_tf32(aS[jt], ak, bS);
                }
            }
            const float b0 = bv[i0], b1 = bv[i1];
#pragma unroll
            for (int jt = 0; jt < 4; jt++) {
                const int jc = wn + jt * 8 + 2 * tg;
                // T = I + strict_tril(beta_i * KK)
                W_f[i0 * DP + jc]     = (jc     < i0) ? b0 * aT[jt][0] : (jc     == i0 ? 1.f : 0.f);
                W_f[i0 * DP + jc + 1] = (jc + 1 < i0) ? b0 * aT[jt][1] : (jc + 1 == i0 ? 1.f : 0.f);
                W_f[i1 * DP + jc]     = (jc     < i1) ? b1 * aT[jt][2] : (jc     == i1 ? 1.f : 0.f);
                W_f[i1 * DP + jc + 1] = (jc + 1 < i1) ? b1 * aT[jt][3] : (jc + 1 == i1 ? 1.f : 0.f);
                // masked QK (j<=i), stored transposed [j][i] as tf32
                QK_t[jc * DP + i0]       = tfbits((jc     <= i0) ? aQ[jt][0] : 0.f);
                QK_t[(jc + 1) * DP + i0] = tfbits((jc + 1 <= i0) ? aQ[jt][1] : 0.f);
                QK_t[jc * DP + i1]       = tfbits((jc     <= i1) ? aQ[jt][2] : 0.f);
                QK_t[(jc + 1) * DP + i1] = tfbits((jc + 1 <= i1) ? aQ[jt][3] : 0.f);
                // U = beta_i * (V - K S)
                U_f[i0 * DP + jc]     = b0 * (U_f[i0 * DP + jc]     - aS[jt][0]);
                U_f[i0 * DP + jc + 1] = b0 * (U_f[i0 * DP + jc + 1] - aS[jt][1]);
                U_f[i1 * DP + jc]     = b1 * (U_f[i1 * DP + jc]     - aS[jt][2]);
                U_f[i1 * DP + jc + 1] = b1 * (U_f[i1 * DP + jc + 1] - aS[jt][3]);
            }
        }
        __syncthreads();

        // ---- D: blocked forward substitution (unit lower W) ----
        // diag block 0
        if (tid < 64) {
            const int e = tid;
#pragma unroll 1
            for (int ii = 1; ii < 16; ii++) {
                const float* wr = &W_f[ii * DP];
                float s = 0.f;
                for (int j = 0; j < ii; j++) s += wr[j] * U_f[j * DP + e];
                U_f[ii * DP + e] -= s;
            }
        }
        __syncthreads();
#pragma unroll 1
        for (int br = 1; br < 4; br++) {
            // off-diagonal update: rows [16br,16br+16) -= W[:,0:16br] * U[0:16br]
            {
                const int e  = tid & 63;
                const int rl = tid >> 6;
#pragma unroll
                for (int rep = 0; rep < 4; rep++) {
                    const int row = br * 16 + rep * 4 + rl;
                    const float* wr = &W_f[row * DP];
                    float a0 = 0.f, a1 = 0.f, a2 = 0.f, a3 = 0.f;
                    for (int j = 0; j < br * 16; j += 4) {
                        a0 += wr[j]     * U_f[j * DP + e];
                        a1 += wr[j + 1] * U_f[(j + 1) * DP + e];
                        a2 += wr[j + 2] * U_f[(j + 2) * DP + e];
                        a3 += wr[j + 3] * U_f[(j + 3) * DP + e];
                    }
                    U_f[row * DP + e] -= (a0 + a1) + (a2 + a3);
                }
            }
            __syncthreads();
            // diagonal 16x16 solve
            if (tid < 64) {
                const int e = tid;
                const int bs = br * 16;
#pragma unroll 1
                for (int ii = 1; ii < 16; ii++) {
                    const float* wr = &W_f[(bs + ii) * DP + bs];
                    float s = 0.f;
                    for (int j = 0; j < ii; j++) s += wr[j] * U_f[(bs + j) * DP + e];
                    U_f[(bs + ii) * DP + e] -= s;
                }
            }
            __syncthreads();
        }

        // ---- E: U -> tf32 ----
        {
#pragma unroll
            for (int r = 0; r < 16; r++) {
                const int idx = r * 256 + tid;
                const int ii = idx >> 6, e = idx & 63;
                U_t[ii * DP + e] = tfbits(U_f[ii * DP + e]);
            }
        }
        __syncthreads();

        // ---- F: mma set 2: O = Q S + maskQK U ; dS = K^T U ----
        {
            float aO[4][4], aSu[4][4];
#pragma unroll
            for (int jt = 0; jt < 4; jt++)
#pragma unroll
                for (int r = 0; r < 4; r++) { aO[jt][r] = 0.f; aSu[jt][r] = 0.f; }

#pragma unroll
            for (int ks = 0; ks < 64; ks += 8) {
                uint32_t aq[4], a2[4], a3[4];
                aq[0] = __float_as_uint(q_t[(ks + tg) * DP + i0]);
                aq[1] = __float_as_uint(q_t[(ks + tg) * DP + i1]);
                aq[2] = __float_as_uint(q_t[(ks + 4 + tg) * DP + i0]);
                aq[3] = __float_as_uint(q_t[(ks + 4 + tg) * DP + i1]);
                a2[0] = __float_as_uint(QK_t[(ks + tg) * DP + i0]);
                a2[1] = __float_as_uint(QK_t[(ks + tg) * DP + i1]);
                a2[2] = __float_as_uint(QK_t[(ks + 4 + tg) * DP + i0]);
                a2[3] = __float_as_uint(QK_t[(ks + 4 + tg) * DP + i1]);
                a3[0] = __float_as_uint(kr_t[(ks + tg) * DP + i0]);
                a3[1] = __float_as_uint(kr_t[(ks + tg) * DP + i1]);
                a3[2] = __float_as_uint(kr_t[(ks + 4 + tg) * DP + i0]);
                a3[3] = __float_as_uint(kr_t[(ks + 4 + tg) * DP + i1]);
#pragma unroll
                for (int jt = 0; jt < 4; jt++) {
                    const int nc = wn + jt * 8 + g;
                    uint32_t bS[2], bU[2];
                    bS[0] = __float_as_uint(S_t[(ks + tg) * DP + nc]);
                    bS[1] = __float_as_uint(S_t[(ks + 4 + tg) * DP + nc]);
                    bU[0] = __float_as_uint(U_t[(ks + tg) * DP + nc]);
                    bU[1] = __float_as_uint(U_t[(ks + 4 + tg) * DP + nc]);
                    mma_tf32(aO[jt], aq, bS);   // Q S
                    mma_tf32(aO[jt], a2, bU);   // maskQK U
                    mma_tf32(aSu[jt], a3, bU);  // K^T U
                }
            }
            __syncthreads();   // all reads of q_t/S_t done before overwrite

            // epilogue: stage O transposed [e][i] into q_t (fp32); update S
#pragma unroll
            for (int jt = 0; jt < 4; jt++) {
                const int ec = wn + jt * 8 + 2 * tg;
                q_t[ec * DP + i0]       = aO[jt][0];
                q_t[(ec + 1) * DP + i0] = aO[jt][1];
                q_t[ec * DP + i1]       = aO[jt][2];
                q_t[(ec + 1) * DP + i1] = aO[jt][3];

                float s00 = S_f[i0 * DP + ec]     + aSu[jt][0];
                float s01 = S_f[i0 * DP + ec + 1] + aSu[jt][1];
                float s10 = S_f[i1 * DP + ec]     + aSu[jt][2];
                float s11 = S_f[i1 * DP + ec + 1] + aSu[jt][3];
                S_f[i0 * DP + ec]     = s00;  S_t[i0 * DP + ec]     = tfbits(s00);
                S_f[i0 * DP + ec + 1] = s01;  S_t[i0 * DP + ec + 1] = tfbits(s01);
                S_f[i1 * DP + ec]     = s10;  S_t[i1 * DP + ec]     = tfbits(s10);
                S_f[i1 * DP + ec + 1] = s11;  S_t[i1 * DP + ec + 1] = tfbits(s11);
            }
        }
        __syncthreads();

        // ---- G: write O chunk (coalesced, channel-major) ----
        {
            float* dst = ogp + (size_t)ld * L_ + off + li0;
#pragma unroll
            for (int u = 0; u < 16; u += 4)
                *(float4*)(dst + u) = *(float4*)&q_t[ld * DP + li0 + u];
        }
        __syncthreads();
    }
}

// ---------------- launch ----------------
extern "C" void kernel_launch(void* const* d_in, const int* in_sizes, int n_in,
                              void* d_out, int out_size)
{
    const float* x  = (const float*)d_in[0];
    const float* Wq = (const float*)d_in[1];
    const float* Wk = (const float*)d_in[2];
    const float* Wv = (const float*)d_in[3];
    const float* Wb = (const float*)d_in[4];
    const float* Wo = (const float*)d_in[5];
    float* out = (float*)d_out;

    float *qp, *kp, *vp, *op, *bp;
    cudaGetSymbolAddress((void**)&qp, g_q);
    cudaGetSymbolAddress((void**)&kp, g_k);
    cudaGetSymbolAddress((void**)&vp, g_v);
    cudaGetSymbolAddress((void**)&op, g_o);
    cudaGetSymbolAddress((void**)&bp, g_beta);

    const int smemDelta = (9 * 64 * DP + 64) * (int)sizeof(float);
    cudaFuncSetAttribute(delta_mma, cudaFuncAttributeMaxDynamicSharedMemorySize, smemDelta);

    dim3 blk(256);
    beta_kernel<<<128, blk>>>(x, Wb, bp);
    gemm_tf32<0, 3><<<dim3(256, 6, 3), blk>>>(x, Wq, Wk, Wv, nullptr, qp, kp, vp);
    delta_mma<<<96, blk, smemDelta>>>(qp, kp, vp, bp, op);
    gemm_tf32<1, 1><<<dim3(256, 6, 1), blk>>>(op, Wo, nullptr, nullptr, x, out, nullptr, nullptr);
}

// round 5
// speedup vs baseline: 1.2497x; 1.0000x over previous
#include <cuda_runtime.h>
#include <cstdint>
#include <cstdio>

#define B_   8
#define C_   768
#define L_   4096
#define NH_  12
#define D_   64
#define BH_  (B_*NH_)
#define SPAD 136
#define DP   72   // delta smem row pad (floats): conflict-free mma frag loads

// ---------------- scratch ----------------
__device__ float g_q[(size_t)B_ * C_ * L_];
__device__ float g_k[(size_t)B_ * C_ * L_];
__device__ float g_v[(size_t)B_ * C_ * L_];
__device__ float g_o[(size_t)B_ * C_ * L_];
__device__ float g_beta[(size_t)BH_ * L_];

__device__ __forceinline__ uint32_t f2tf(float f) {
    uint32_t r;
    asm("cvt.rna.tf32.f32 %0, %1;" : "=r"(r) : "f"(f));
    return r;
}
__device__ __forceinline__ float tfbits(float f) {   // store tf32 bit pattern as float
    return __uint_as_float(f2tf(f));
}

__device__ __forceinline__ void mma_tf32(float c[4], const uint32_t a[4], const uint32_t b[2]) {
    asm volatile(
        "mma.sync.aligned.m16n8k8.row.col.f32.tf32.tf32.f32 "
        "{%0,%1,%2,%3}, {%4,%5,%6,%7}, {%8,%9}, {%0,%1,%2,%3};"
        : "+f"(c[0]), "+f"(c[1]), "+f"(c[2]), "+f"(c[3])
        : "r"(a[0]), "r"(a[1]), "r"(a[2]), "r"(a[3]), "r"(b[0]), "r"(b[1]));
}

// ---------------- tf32 tensor-core GEMM (unchanged from R3) ----------------
template<int EPI, int NZ>
__global__ __launch_bounds__(256) void gemm_tf32(
    const float* __restrict__ A,
    const float* __restrict__ W0, const float* __restrict__ W1, const float* __restrict__ W2,
    const float* __restrict__ R,
    float* __restrict__ O0, float* __restrict__ O1, float* __restrict__ O2)
{
    __shared__ uint32_t As[2][16][SPAD];
    __shared__ uint32_t Bs[2][16][SPAD];

    const int tid  = threadIdx.x;
    const int wid  = tid >> 5;
    const int lane = tid & 31;
    const int m0   = blockIdx.x * 128;
    const int b    = m0 >> 12;
    const int l0   = m0 & 4095;
    const int n0   = blockIdx.y * 128;

    const float* W;
    float* Out;
    if (NZ == 3) {
        const int z = blockIdx.z;
        W   = (z == 0) ? W0 : (z == 1) ? W1 : W2;
        Out = (z == 0) ? O0 : (z == 1) ? O1 : O2;
    } else {
        W = W0; Out = O0;
    }
    const float* Ab = A + (size_t)b * C_ * L_ + l0;

    const int lk = tid >> 5;
    const int lc = (tid & 31) << 2;

    const int wm = (wid & 3) * 32;
    const int wn = (wid >> 2) * 64;
    const int g  = lane >> 2;
    const int tg = lane & 3;

    float acc[2][8][4];
#pragma unroll
    for (int mf = 0; mf < 2; mf++)
#pragma unroll
        for (int j = 0; j < 8; j++)
#pragma unroll
            for (int r = 0; r < 4; r++) acc[mf][j][r] = 0.f;

    float4 pa0, pa1, pw0, pw1;
    pa0 = *(const float4*)(Ab + (size_t)lk * L_ + lc);
    pa1 = *(const float4*)(Ab + (size_t)(lk + 8) * L_ + lc);
    pw0 = *(const float4*)(W + (size_t)lk * C_ + n0 + lc);
    pw1 = *(const float4*)(W + (size_t)(lk + 8) * C_ + n0 + lc);
    {
        uint32_t* d0 = &As[0][lk][lc];
        uint32_t* d1 = &As[0][lk + 8][lc];
        d0[0] = f2tf(pa0.x); d0[1] = f2tf(pa0.y); d0[2] = f2tf(pa0.z); d0[3] = f2tf(pa0.w);
        d1[0] = f2tf(pa1.x); d1[1] = f2tf(pa1.y); d1[2] = f2tf(pa1.z); d1[3] = f2tf(pa1.w);
        uint32_t* e0 = &Bs[0][lk][lc];
        uint32_t* e1 = &Bs[0][lk + 8][lc];
        e0[0] = f2tf(pw0.x); e0[1] = f2tf(pw0.y); e0[2] = f2tf(pw0.z); e0[3] = f2tf(pw0.w);
        e1[0] = f2tf(pw1.x); e1[1] = f2tf(pw1.y); e1[2] = f2tf(pw1.z); e1[3] = f2tf(pw1.w);
    }
    __syncthreads();

    for (int k0 = 0; k0 < C_; k0 += 16) {
        const int  buf  = (k0 >> 4) & 1;
        const bool more = (k0 + 16) < C_;
        if (more) {
            pa0 = *(const float4*)(Ab + (size_t)(k0 + 16 + lk) * L_ + lc);
            pa1 = *(const float4*)(Ab + (size_t)(k0 + 24 + lk) * L_ + lc);
            pw0 = *(const float4*)(W + (size_t)(k0 + 16 + lk) * C_ + n0 + lc);
            pw1 = *(const float4*)(W + (size_t)(k0 + 24 + lk) * C_ + n0 + lc);
        }
#pragma unroll
        for (int ks = 0; ks < 16; ks += 8) {
            uint32_t af[2][4], bf[8][2];
#pragma unroll
            for (int mf = 0; mf < 2; mf++) {
                const int mr = wm + mf * 16 + g;
                af[mf][0] = As[buf][ks + tg][mr];
                af[mf][1] = As[buf][ks + tg][mr + 8];
                af[mf][2] = As[buf][ks + 4 + tg][mr];
                af[mf][3] = As[buf][ks + 4 + tg][mr + 8];
            }
#pragma unroll
            for (int j = 0; j < 8; j++) {
                const int nc = wn + j * 8 + g;
                bf[j][0] = Bs[buf][ks + tg][nc];
                bf[j][1] = Bs[buf][ks + 4 + tg][nc];
            }
#pragma unroll
            for (int mf = 0; mf < 2; mf++)
#pragma unroll
                for (int j = 0; j < 8; j++)
                    mma_tf32(acc[mf][j], af[mf], bf[j]);
        }
        if (more) {
            uint32_t* d0 = &As[buf ^ 1][lk][lc];
            uint32_t* d1 = &As[buf ^ 1][lk + 8][lc];
            d0[0] = f2tf(pa0.x); d0[1] = f2tf(pa0.y); d0[2] = f2tf(pa0.z); d0[3] = f2tf(pa0.w);
            d1[0] = f2tf(pa1.x); d1[1] = f2tf(pa1.y); d1[2] = f2tf(pa1.z); d1[3] = f2tf(pa1.w);
            uint32_t* e0 = &Bs[buf ^ 1][lk][lc];
            uint32_t* e1 = &Bs[buf ^ 1][lk + 8][lc];
            e0[0] = f2tf(pw0.x); e0[1] = f2tf(pw0.y); e0[2] = f2tf(pw0.z); e0[3] = f2tf(pw0.w);
            e1[0] = f2tf(pw1.x); e1[1] = f2tf(pw1.y); e1[2] = f2tf(pw1.z); e1[3] = f2tf(pw1.w);
        }
        __syncthreads();
    }

    float* stage = (float*)&As[0][0][0];
#pragma unroll 1
    for (int s = 0; s < 4; s++) {
#pragma unroll
        for (int mf = 0; mf < 2; mf++)
#pragma unroll
            for (int j = 0; j < 8; j++) {
                if (((wn + j * 8) >> 5) != s) continue;
                const int n = (wn + j * 8 + tg * 2) & 31;
                const int m = wm + mf * 16 + g;
                float v0 = acc[mf][j][0], v1 = acc[mf][j][1];
                float v2 = acc[mf][j][2], v3 = acc[mf][j][3];
                if (EPI == 0) {
                    v0 = v0 / (1.f + __expf(-v0));
                    v1 = v1 / (1.f + __expf(-v1));
                    v2 = v2 / (1.f + __expf(-v2));
                    v3 = v3 / (1.f + __expf(-v3));
                }
                stage[n * 132 + m]           = v0;
                stage[(n + 1) * 132 + m]     = v1;
                stage[n * 132 + m + 8]       = v2;
                stage[(n + 1) * 132 + m + 8] = v3;
            }
        __syncthreads();
        {
            const int nr   = tid >> 3;
            const int lcol = (tid & 7) << 4;
            const size_t gb = ((size_t)(b * C_ + n0 + s * 32 + nr)) * L_ + l0 + lcol;
            float v[16];
#pragma unroll
            for (int t = 0; t < 16; t++) v[t] = stage[nr * 132 + lcol + t];
            if (EPI == 1) {
                const float* r = R + gb;
#pragma unroll
                for (int t = 0; t < 16; t++) v[t] += r[t];
            }
            float* dst = Out + gb;
            *(float4*)(dst)      = *(float4*)(v);
            *(float4*)(dst + 4)  = *(float4*)(v + 4);
            *(float4*)(dst + 8)  = *(float4*)(v + 8);
            *(float4*)(dst + 12) = *(float4*)(v + 12);
        }
        __syncthreads();
    }
}

// ---------------- beta = sigmoid(t @ Wb) ----------------
__global__ __launch_bounds__(256) void beta_kernel(
    const float* __restrict__ X, const float* __restrict__ Wb,
    float* __restrict__ Beta)
{
    __shared__ float As[16][256];
    __shared__ float Ws[16][12];
    const int tid = threadIdx.x;
    const int m0  = blockIdx.x * 256;
    const int b   = m0 >> 12;
    const int l0  = m0 & 4095;
    const float* Ab = X + (size_t)b * C_ * L_ + l0;

    float acc[12];
#pragma unroll
    for (int h = 0; h < 12; h++) acc[h] = 0.f;

    for (int k0 = 0; k0 < C_; k0 += 16) {
#pragma unroll
        for (int kk = 0; kk < 16; kk++) As[kk][tid] = Ab[(size_t)(k0 + kk) * L_ + tid];
        if (tid < 192) Ws[tid / 12][tid % 12] = Wb[(size_t)(k0 + tid / 12) * 12 + (tid % 12)];
        __syncthreads();
#pragma unroll
        for (int kk = 0; kk < 16; kk++) {
            float a = As[kk][tid];
#pragma unroll
            for (int h = 0; h < 12; h++) acc[h] += a * Ws[kk][h];
        }
        __syncthreads();
    }
#pragma unroll
    for (int h = 0; h < 12; h++) {
        Beta[((size_t)(b * NH_ + h)) * L_ + l0 + tid] = 1.f / (1.f + __expf(-acc[h]));
    }
}

// ---------------- delta rule, tensor-core version ----------------
// 1 CTA per (b,h). 64 sequential chunks of 64 tokens. All 64x64x64 matmuls via
// tf32 mma m16n8k8 (8 warps, warp tile 16x32). State S kept fp32; tf32 shadow
// regenerated after each update. Triangular solve: blocked-16 forward subst.
__global__ __launch_bounds__(256) void delta_mma(
    const float* __restrict__ gq, const float* __restrict__ gk,
    const float* __restrict__ gv, const float* __restrict__ gb,
    float* __restrict__ go)
{
    extern __shared__ float sm[];
    float* S_f  = sm;               // [d][e] fp32 state
    float* S_t  = S_f  + 64 * DP;   // [d][e] tf32
    float* q_t  = S_t  + 64 * DP;   // [d][i] tf32 (reused as O stage [e][i] fp32)
    float* k_t  = q_t  + 64 * DP;   // [d][i] tf32
    float* kr_t = k_t  + 64 * DP;   // [i][d] tf32
    float* U_f  = kr_t + 64 * DP;   // [i][e] fp32 rhs -> U
    float* U_t  = U_f  + 64 * DP;   // [i][e] tf32
    float* W_f  = U_t  + 64 * DP;   // [i][j] fp32 unit-lower T
    float* QK_t = W_f  + 64 * DP;   // [j][i] tf32 masked QK (transposed)
    float* bv   = QK_t + 64 * DP;   // [64]

    const int tid  = threadIdx.x;
    const int wid  = tid >> 5;
    const int lane = tid & 31;
    const int wm   = (wid & 3) * 16;   // warp m block (i or d rows)
    const int wn   = (wid >> 2) * 32;  // warp n block
    const int g    = lane >> 2;
    const int tg   = lane & 3;
    const int i0   = wm + g;
    const int i1   = wm + g + 8;

    const int bh = blockIdx.x;
    const int b  = bh / NH_, h = bh % NH_;
    const size_t base = ((size_t)(b * C_ + h * D_)) * L_;
    const float* qgp = gq + base;
    const float* kgp = gk + base;
    const float* vgp = gv + base;
    const float* bgp = gb + (size_t)bh * L_;
    float* ogp = go + base;

    for (int i = tid; i < 2 * 64 * DP; i += 256) S_f[i] = 0.f;   // S_f and S_t
    __syncthreads();

    const int ld  = tid >> 2;          // 0..63 row for load/store
    const int li0 = (tid & 3) << 4;    // 0,16,32,48

    for (int c = 0; c < 64; c++) {
        const int off = c * 64;

        // ---- A: load q,k (raw fp32 into q_t/k_t), v (transposed into U_f), beta ----
        {
            const float* qrow = qgp + (size_t)ld * L_ + off + li0;
            const float* krow = kgp + (size_t)ld * L_ + off + li0;
            const float* vrow = vgp + (size_t)ld * L_ + off + li0;
#pragma unroll
            for (int u = 0; u < 16; u += 4) {
                float4 qv = *(const float4*)(qrow + u);
                float4 kv = *(const float4*)(krow + u);
                float4 vv = *(const float4*)(vrow + u);
                *(float4*)&q_t[ld * DP + li0 + u] = qv;
                *(float4*)&k_t[ld * DP + li0 + u] = kv;
                U_f[(li0 + u + 0) * DP + ld] = vv.x;
                U_f[(li0 + u + 1) * DP + ld] = vv.y;
                U_f[(li0 + u + 2) * DP + ld] = vv.z;
                U_f[(li0 + u + 3) * DP + ld] = vv.w;
            }
            if (tid < 64) bv[tid] = bgp[off + tid];
        }
        __syncthreads();

        // ---- B: l2norm q,k per token; convert to tf32; build kr_t ----
        {
            const int tok = tid >> 2;
            const int d0  = (tid & 3) << 4;
            float sq = 0.f, sk = 0.f;
#pragma unroll
            for (int d = d0; d < d0 + 16; d++) {
                float qv = q_t[d * DP + tok]; sq += qv * qv;
                float kv = k_t[d * DP + tok]; sk += kv * kv;
            }
            sq += __shfl_xor_sync(0xFFFFFFFFu, sq, 1);
            sq += __shfl_xor_sync(0xFFFFFFFFu, sq, 2);
            sk += __shfl_xor_sync(0xFFFFFFFFu, sk, 1);
            sk += __shfl_xor_sync(0xFFFFFFFFu, sk, 2);
            const float rq = rsqrtf(sq + 1e-6f);
            const float rk = rsqrtf(sk + 1e-6f);
#pragma unroll
            for (int d = d0; d < d0 + 16; d++) {
                q_t[d * DP + tok] = tfbits(q_t[d * DP + tok] * rq);
                float kv = k_t[d * DP + tok] * rk;
                float kb = tfbits(kv);
                k_t[d * DP + tok] = kb;
                kr_t[tok * DP + d] = kb;
            }
        }
        __syncthreads();

        // ---- C: mma set 1: T_raw = K K^T, QK = Q K^T, KS = K S  (contract d) ----
        {
            float aT[4][4], aQ[4][4], aS[4][4];
#pragma unroll
            for (int jt = 0; jt < 4; jt++)
#pragma unroll
                for (int r = 0; r < 4; r++) { aT[jt][r] = 0.f; aQ[jt][r] = 0.f; aS[jt][r] = 0.f; }

#pragma unroll
            for (int ks = 0; ks < 64; ks += 8) {
                uint32_t ak[4], aq[4];
                ak[0] = __float_as_uint(k_t[(ks + tg) * DP + i0]);
                ak[1] = __float_as_uint(k_t[(ks + tg) * DP + i1]);
                ak[2] = __float_as_uint(k_t[(ks + 4 + tg) * DP + i0]);
                ak[3] = __float_as_uint(k_t[(ks + 4 + tg) * DP + i1]);
                aq[0] = __float_as_uint(q_t[(ks + tg) * DP + i0]);
                aq[1] = __float_as_uint(q_t[(ks + tg) * DP + i1]);
                aq[2] = __float_as_uint(q_t[(ks + 4 + tg) * DP + i0]);
                aq[3] = __float_as_uint(q_t[(ks + 4 + tg) * DP + i1]);
#pragma unroll
                for (int jt = 0; jt < 4; jt++) {
                    const int nc = wn + jt * 8 + g;
                    uint32_t bk[2], bS[2];
                    bk[0] = __float_as_uint(k_t[(ks + tg) * DP + nc]);
                    bk[1] = __float_as_uint(k_t[(ks + 4 + tg) * DP + nc]);
                    bS[0] = __float_as_uint(S_t[(ks + tg) * DP + nc]);
                    bS[1] = __float_as_uint(S_t[(ks + 4 + tg) * DP + nc]);
                    mma_tf32(aT[jt], ak, bk);
                    mma_tf32(aQ[jt], aq, bk);
                    mma_tf32(aS[jt], ak, bS);
                }
            }
            const float b0 = bv[i0], b1 = bv[i1];
#pragma unroll
            for (int jt = 0; jt < 4; jt++) {
                const int jc = wn + jt * 8 + 2 * tg;
                // T = I + strict_tril(beta_i * KK)
                W_f[i0 * DP + jc]     = (jc     < i0) ? b0 * aT[jt][0] : (jc     == i0 ? 1.f : 0.f);
                W_f[i0 * DP + jc + 1] = (jc + 1 < i0) ? b0 * aT[jt][1] : (jc + 1 == i0 ? 1.f : 0.f);
                W_f[i1 * DP + jc]     = (jc     < i1) ? b1 * aT[jt][2] : (jc     == i1 ? 1.f : 0.f);
                W_f[i1 * DP + jc + 1] = (jc + 1 < i1) ? b1 * aT[jt][3] : (jc + 1 == i1 ? 1.f : 0.f);
                // masked QK (j<=i), stored transposed [j][i] as tf32
                QK_t[jc * DP + i0]       = tfbits((jc     <= i0) ? aQ[jt][0] : 0.f);
                QK_t[(jc + 1) * DP + i0] = tfbits((jc + 1 <= i0) ? aQ[jt][1] : 0.f);
                QK_t[jc * DP + i1]       = tfbits((jc     <= i1) ? aQ[jt][2] : 0.f);
                QK_t[(jc + 1) * DP + i1] = tfbits((jc + 1 <= i1) ? aQ[jt][3] : 0.f);
                // U = beta_i * (V - K S)
                U_f[i0 * DP + jc]     = b0 * (U_f[i0 * DP + jc]     - aS[jt][0]);
                U_f[i0 * DP + jc + 1] = b0 * (U_f[i0 * DP + jc + 1] - aS[jt][1]);
                U_f[i1 * DP + jc]     = b1 * (U_f[i1 * DP + jc]     - aS[jt][2]);
                U_f[i1 * DP + jc + 1] = b1 * (U_f[i1 * DP + jc + 1] - aS[jt][3]);
            }
        }
        __syncthreads();

        // ---- D: blocked forward substitution (unit lower W) ----
        // diag block 0
        if (tid < 64) {
            const int e = tid;
#pragma unroll 1
            for (int ii = 1; ii < 16; ii++) {
                const float* wr = &W_f[ii * DP];
                float s = 0.f;
                for (int j = 0; j < ii; j++) s += wr[j] * U_f[j * DP + e];
                U_f[ii * DP + e] -= s;
            }
        }
        __syncthreads();
#pragma unroll 1
        for (int br = 1; br < 4; br++) {
            // off-diagonal update: rows [16br,16br+16) -= W[:,0:16br] * U[0:16br]
            {
                const int e  = tid & 63;
                const int rl = tid >> 6;
#pragma unroll
                for (int rep = 0; rep < 4; rep++) {
                    const int row = br * 16 + rep * 4 + rl;
                    const float* wr = &W_f[row * DP];
                    float a0 = 0.f, a1 = 0.f, a2 = 0.f, a3 = 0.f;
                    for (int j = 0; j < br * 16; j += 4) {
                        a0 += wr[j]     * U_f[j * DP + e];
                        a1 += wr[j + 1] * U_f[(j + 1) * DP + e];
                        a2 += wr[j + 2] * U_f[(j + 2) * DP + e];
                        a3 += wr[j + 3] * U_f[(j + 3) * DP + e];
                    }
                    U_f[row * DP + e] -= (a0 + a1) + (a2 + a3);
                }
            }
            __syncthreads();
            // diagonal 16x16 solve
            if (tid < 64) {
                const int e = tid;
                const int bs = br * 16;
#pragma unroll 1
                for (int ii = 1; ii < 16; ii++) {
                    const float* wr = &W_f[(bs + ii) * DP + bs];
                    float s = 0.f;
                    for (int j = 0; j < ii; j++) s += wr[j] * U_f[(bs + j) * DP + e];
                    U_f[(bs + ii) * DP + e] -= s;
                }
            }
            __syncthreads();
        }

        // ---- E: U -> tf32 ----
        {
#pragma unroll
            for (int r = 0; r < 16; r++) {
                const int idx = r * 256 + tid;
                const int ii = idx >> 6, e = idx & 63;
                U_t[ii * DP + e] = tfbits(U_f[ii * DP + e]);
            }
        }
        __syncthreads();

        // ---- F: mma set 2: O = Q S + maskQK U ; dS = K^T U ----
        {
            float aO[4][4], aSu[4][4];
#pragma unroll
            for (int jt = 0; jt < 4; jt++)
#pragma unroll
                for (int r = 0; r < 4; r++) { aO[jt][r] = 0.f; aSu[jt][r] = 0.f; }

#pragma unroll
            for (int ks = 0; ks < 64; ks += 8) {
                uint32_t aq[4], a2[4], a3[4];
                aq[0] = __float_as_uint(q_t[(ks + tg) * DP + i0]);
                aq[1] = __float_as_uint(q_t[(ks + tg) * DP + i1]);
                aq[2] = __float_as_uint(q_t[(ks + 4 + tg) * DP + i0]);
                aq[3] = __float_as_uint(q_t[(ks + 4 + tg) * DP + i1]);
                a2[0] = __float_as_uint(QK_t[(ks + tg) * DP + i0]);
                a2[1] = __float_as_uint(QK_t[(ks + tg) * DP + i1]);
                a2[2] = __float_as_uint(QK_t[(ks + 4 + tg) * DP + i0]);
                a2[3] = __float_as_uint(QK_t[(ks + 4 + tg) * DP + i1]);
                a3[0] = __float_as_uint(kr_t[(ks + tg) * DP + i0]);
                a3[1] = __float_as_uint(kr_t[(ks + tg) * DP + i1]);
                a3[2] = __float_as_uint(kr_t[(ks + 4 + tg) * DP + i0]);
                a3[3] = __float_as_uint(kr_t[(ks + 4 + tg) * DP + i1]);
#pragma unroll
                for (int jt = 0; jt < 4; jt++) {
                    const int nc = wn + jt * 8 + g;
                    uint32_t bS[2], bU[2];
                    bS[0] = __float_as_uint(S_t[(ks + tg) * DP + nc]);
                    bS[1] = __float_as_uint(S_t[(ks + 4 + tg) * DP + nc]);
                    bU[0] = __float_as_uint(U_t[(ks + tg) * DP + nc]);
                    bU[1] = __float_as_uint(U_t[(ks + 4 + tg) * DP + nc]);
                    mma_tf32(aO[jt], aq, bS);   // Q S
                    mma_tf32(aO[jt], a2, bU);   // maskQK U
                    mma_tf32(aSu[jt], a3, bU);  // K^T U
                }
            }
            __syncthreads();   // all reads of q_t/S_t done before overwrite

            // epilogue: stage O transposed [e][i] into q_t (fp32); update S
#pragma unroll
            for (int jt = 0; jt < 4; jt++) {
                const int ec = wn + jt * 8 + 2 * tg;
                q_t[ec * DP + i0]       = aO[jt][0];
                q_t[(ec + 1) * DP + i0] = aO[jt][1];
                q_t[ec * DP + i1]       = aO[jt][2];
                q_t[(ec + 1) * DP + i1] = aO[jt][3];

                float s00 = S_f[i0 * DP + ec]     + aSu[jt][0];
                float s01 = S_f[i0 * DP + ec + 1] + aSu[jt][1];
                float s10 = S_f[i1 * DP + ec]     + aSu[jt][2];
                float s11 = S_f[i1 * DP + ec + 1] + aSu[jt][3];
                S_f[i0 * DP + ec]     = s00;  S_t[i0 * DP + ec]     = tfbits(s00);
                S_f[i0 * DP + ec + 1] = s01;  S_t[i0 * DP + ec + 1] = tfbits(s01);
                S_f[i1 * DP + ec]     = s10;  S_t[i1 * DP + ec]     = tfbits(s10);
                S_f[i1 * DP + ec + 1] = s11;  S_t[i1 * DP + ec + 1] = tfbits(s11);
            }
        }
        __syncthreads();

        // ---- G: write O chunk (coalesced, channel-major) ----
        {
            float* dst = ogp + (size_t)ld * L_ + off + li0;
#pragma unroll
            for (int u = 0; u < 16; u += 4)
                *(float4*)(dst + u) = *(float4*)&q_t[ld * DP + li0 + u];
        }
        __syncthreads();
    }
}

// ---------------- launch ----------------
extern "C" void kernel_launch(void* const* d_in, const int* in_sizes, int n_in,
                              void* d_out, int out_size)
{
    const float* x  = (const float*)d_in[0];
    const float* Wq = (const float*)d_in[1];
    const float* Wk = (const float*)d_in[2];
    const float* Wv = (const float*)d_in[3];
    const float* Wb = (const float*)d_in[4];
    const float* Wo = (const float*)d_in[5];
    float* out = (float*)d_out;

    float *qp, *kp, *vp, *op, *bp;
    cudaGetSymbolAddress((void**)&qp, g_q);
    cudaGetSymbolAddress((void**)&kp, g_k);
    cudaGetSymbolAddress((void**)&vp, g_v);
    cudaGetSymbolAddress((void**)&op, g_o);
    cudaGetSymbolAddress((void**)&bp, g_beta);

    const int smemDelta = (9 * 64 * DP + 64) * (int)sizeof(float);
    cudaFuncSetAttribute(delta_mma, cudaFuncAttributeMaxDynamicSharedMemorySize, smemDelta);

    dim3 blk(256);
    beta_kernel<<<128, blk>>>(x, Wb, bp);
    gemm_tf32<0, 3><<<dim3(256, 6, 3), blk>>>(x, Wq, Wk, Wv, nullptr, qp, kp, vp);
    delta_mma<<<96, blk, smemDelta>>>(qp, kp, vp, bp, op);
    gemm_tf32<1, 1><<<dim3(256, 6, 1), blk>>>(op, Wo, nullptr, nullptr, x, out, nullptr, nullptr);
}